// round 1
// baseline (speedup 1.0000x reference)
#include <cuda_runtime.h>
#include <math.h>

#define MODEL_DIM 128
#define N_FRAMES 128
#define N_SAMPLES 32768
#define N_TABLES 16
#define TABLE_SIZE 512
#define BATCH 8
#define INV_STD 100.0f
#define GAUSS_SCALE 39.894228040143274f   // 1/(0.01*sqrt(2*pi))
#define BAND_HALF 64

// ------------------- scratch (static device globals; no runtime alloc) ---------
__device__ float g_env_frames[BATCH][N_FRAMES];   // (mlp out)^2
__device__ float g_freq_frames[BATCH][N_FRAMES];  // (mlp out)^2
__device__ float g_table[BATCH][TABLE_SIZE];      // normalized selected table
__device__ float g_values[BATCH];
__device__ int   g_idx[BATCH];
__device__ float g_phase[BATCH][N_SAMPLES];
__device__ float g_env[BATCH][N_SAMPLES];

// ---------------------------------------------------------------------------
// Head kernel: 3 blocks (tc / env / freq heads), 1024 threads each.
// Each block runs a 3-layer MLP on the 8x128 input.
// ---------------------------------------------------------------------------
__global__ void head_kernel(const float* __restrict__ x,
                            const float* __restrict__ tc_w1, const float* __restrict__ tc_b1,
                            const float* __restrict__ tc_w2, const float* __restrict__ tc_b2,
                            const float* __restrict__ tc_w3, const float* __restrict__ tc_b3,
                            const float* __restrict__ env_w1, const float* __restrict__ env_b1,
                            const float* __restrict__ env_w2, const float* __restrict__ env_b2,
                            const float* __restrict__ env_w3, const float* __restrict__ env_b3,
                            const float* __restrict__ fr_w1, const float* __restrict__ fr_b1,
                            const float* __restrict__ fr_w2, const float* __restrict__ fr_b2,
                            const float* __restrict__ fr_w3, const float* __restrict__ fr_b3)
{
    const int head = blockIdx.x;
    const int tid = threadIdx.x;

    __shared__ float hs[BATCH * MODEL_DIM];
    __shared__ float h2[BATCH * MODEL_DIM];
    __shared__ float out_s[BATCH * 256];     // big enough for tc head (8x256)
    __shared__ float s_scores[BATCH * N_TABLES];

    const float *w1, *b1, *w2, *b2, *w3, *b3;
    int outdim;
    if (head == 0) { w1 = tc_w1;  b1 = tc_b1;  w2 = tc_w2;  b2 = tc_b2;  w3 = tc_w3;  b3 = tc_b3;  outdim = 256; }
    else if (head == 1) { w1 = env_w1; b1 = env_b1; w2 = env_w2; b2 = env_b2; w3 = env_w3; b3 = env_b3; outdim = 128; }
    else { w1 = fr_w1;  b1 = fr_b1;  w2 = fr_w2;  b2 = fr_b2;  w3 = fr_w3;  b3 = fr_b3;  outdim = 128; }

    // load x (8x128)
    hs[tid] = x[tid];
    __syncthreads();

    // layer1: hs -> h2 (leaky relu 0.2)
    {
        int b = tid >> 7, o = tid & 127;
        float acc = b1[o];
        const float* hb = &hs[b * MODEL_DIM];
        #pragma unroll 8
        for (int i = 0; i < MODEL_DIM; i++)
            acc = fmaf(hb[i], w1[i * MODEL_DIM + o], acc);
        h2[tid] = (acc >= 0.0f) ? acc : 0.2f * acc;
    }
    __syncthreads();

    // layer2: h2 -> hs (leaky relu 0.2)
    {
        int b = tid >> 7, o = tid & 127;
        float acc = b2[o];
        const float* hb = &h2[b * MODEL_DIM];
        #pragma unroll 8
        for (int i = 0; i < MODEL_DIM; i++)
            acc = fmaf(hb[i], w2[i * MODEL_DIM + o], acc);
        hs[tid] = (acc >= 0.0f) ? acc : 0.2f * acc;
    }
    __syncthreads();

    // layer3: hs -> out_s (linear)
    for (int oo = tid; oo < BATCH * outdim; oo += 1024) {
        int b = oo / outdim, o = oo - b * outdim;
        float acc = b3[o];
        const float* hb = &hs[b * MODEL_DIM];
        #pragma unroll 8
        for (int i = 0; i < MODEL_DIM; i++)
            acc = fmaf(hb[i], w3[i * outdim + o], acc);
        out_s[oo] = acc;
    }
    __syncthreads();

    if (head == 0) {
        // scores = mean over groups of 16, then argmax/max per batch item
        if (tid < BATCH * N_TABLES) {
            int b = tid >> 4, n = tid & 15;
            float s = 0.0f;
            #pragma unroll
            for (int k = 0; k < 16; k++) s += out_s[b * 256 + n * 16 + k];
            s_scores[tid] = s * (1.0f / 16.0f);
        }
        __syncthreads();
        if (tid < BATCH) {
            float best = s_scores[tid * N_TABLES];
            int bi = 0;
            #pragma unroll
            for (int n = 1; n < N_TABLES; n++) {
                float v = s_scores[tid * N_TABLES + n];
                if (v > best) { best = v; bi = n; }   // first-max on ties, matches argmax
            }
            g_values[tid] = best;
            g_idx[tid] = bi;
        }
    } else if (head == 1) {
        float v = out_s[tid];
        ((float*)g_env_frames)[tid] = v * v;   // env ** 2 BEFORE interpolation
    } else {
        float v = out_s[tid];
        ((float*)g_freq_frames)[tid] = v * v;  // freq = out ** 2 BEFORE interpolation
    }
}

// ---------------------------------------------------------------------------
// Normalize the selected wavetable per batch item: 8 blocks x 256 threads
// ---------------------------------------------------------------------------
__global__ void table_kernel(const float* __restrict__ wavetables)
{
    const int b = blockIdx.x;
    const int tid = threadIdx.x;
    const float* row = wavetables + g_idx[b] * TABLE_SIZE;

    __shared__ float sm[256];
    float m = fmaxf(row[tid], row[tid + 256]);
    sm[tid] = m;
    __syncthreads();
    for (int s = 128; s > 0; s >>= 1) {
        if (tid < s) sm[tid] = fmaxf(sm[tid], sm[tid + s]);
        __syncthreads();
    }
    float denom = sm[0] + 1e-8f;
    g_table[b][tid]       = row[tid] / denom;
    g_table[b][tid + 256] = row[tid + 256] / denom;
}

// ---------------------------------------------------------------------------
// Per-batch: interpolate env & freq to 32768 samples; block-scan cumsum of
// freq -> phase = cumsum % 1.  8 blocks x 1024 threads, 32 samples/thread.
// ---------------------------------------------------------------------------
__global__ void scan_kernel()
{
    const int b = blockIdx.x;
    const int tid = threadIdx.x;
    __shared__ float s_freq[N_FRAMES];
    __shared__ float s_env[N_FRAMES];
    __shared__ float s_w[32];

    if (tid < N_FRAMES) {
        s_freq[tid] = g_freq_frames[b][tid];
        s_env[tid]  = g_env_frames[b][tid];
    }
    __syncthreads();

    const int PER = 32;
    const int t0 = tid * PER;
    float vals[PER];
    float run = 0.0f;

    #pragma unroll
    for (int k = 0; k < PER; k++) {
        int t = t0 + k;
        float pos = ((float)t + 0.5f) * (1.0f / 256.0f) - 0.5f;
        pos = fminf(fmaxf(pos, 0.0f), 127.0f);
        int lo = (int)floorf(pos);
        int hi = min(lo + 1, 127);
        float w = pos - (float)lo;
        float f = s_freq[lo] * (1.0f - w) + s_freq[hi] * w;
        run += f;
        vals[k] = run;
        float e = s_env[lo] * (1.0f - w) + s_env[hi] * w;
        g_env[b][t] = e;
    }

    // block exclusive scan over per-thread totals
    const int lane = tid & 31, wid = tid >> 5;
    float incl = run;
    #pragma unroll
    for (int off = 1; off < 32; off <<= 1) {
        float n = __shfl_up_sync(0xFFFFFFFFu, incl, off);
        if (lane >= off) incl += n;
    }
    if (lane == 31) s_w[wid] = incl;
    __syncthreads();
    if (wid == 0) {
        float v = s_w[lane];
        #pragma unroll
        for (int off = 1; off < 32; off <<= 1) {
            float n = __shfl_up_sync(0xFFFFFFFFu, v, off);
            if (lane >= off) v += n;
        }
        s_w[lane] = v;
    }
    __syncthreads();
    float excl = ((wid > 0) ? s_w[wid - 1] : 0.0f) + (incl - run);

    #pragma unroll
    for (int k = 0; k < PER; k++) {
        float c = excl + vals[k];
        g_phase[b][t0 + k] = fmodf(c, 1.0f);
    }
}

// ---------------------------------------------------------------------------
// sampled[b][t] = (sum_j table[b][j] * K[b][t][j]) * env * values
// Warp per sample; only the ~128-column Gaussian band contributes.
// ---------------------------------------------------------------------------
__global__ void sampled_kernel(float* __restrict__ out)
{
    const int gw = (blockIdx.x * blockDim.x + threadIdx.x) >> 5;
    const int lane = threadIdx.x & 31;
    if (gw >= BATCH * N_SAMPLES) return;
    const int b = gw >> 15;
    const int t = gw & (N_SAMPLES - 1);

    const float phi = g_phase[b][t];
    const int jc = __float2int_rn(phi * 511.0f);
    float acc = 0.0f;

    #pragma unroll
    for (int i = 0; i < 4; i++) {
        int j = jc - BAND_HALF + lane + i * 32;
        if (j >= 0 && j < TABLE_SIZE) {
            float z = ((float)j * (1.0f / 511.0f) - phi) * INV_STD;
            float a = -0.5f * z * z;
            if (a > -87.0f)
                acc = fmaf(g_table[b][j], __expf(a), acc);
        }
    }
    #pragma unroll
    for (int off = 16; off > 0; off >>= 1)
        acc += __shfl_down_sync(0xFFFFFFFFu, acc, off);

    if (lane == 0)
        out[gw] = acc * GAUSS_SCALE * g_env[b][t] * g_values[b];
}

// ---------------------------------------------------------------------------
// sampling_kernel writer: (B, N_SAMPLES, TABLE_SIZE) fp32 = 537 MB.
// One thread per float4. Band-limited predicated __expf; everything outside
// |z| threshold underflows to 0 in fp32 exactly like the reference.
// ---------------------------------------------------------------------------
__global__ void kern_writer(float* __restrict__ out)
{
    const long long idx = (long long)blockIdx.x * blockDim.x + threadIdx.x; // float4 index
    const int t_global = (int)(idx >> 7);          // 128 float4 per 512-col row
    const int c4 = (int)(idx & 127);
    const int b = t_global >> 15;
    const int t = t_global & (N_SAMPLES - 1);

    const float p100 = g_phase[b][t] * INV_STD;    // phi / std
    const float col0 = (float)(c4 * 4);

    float4 v;
    float* vp = &v.x;
    #pragma unroll
    for (int k = 0; k < 4; k++) {
        float z = fmaf(col0 + (float)k, INV_STD / 511.0f, -p100);
        float a = -0.5f * z * z;
        vp[k] = (a > -87.0f) ? (GAUSS_SCALE * __expf(a)) : 0.0f;
    }
    reinterpret_cast<float4*>(out)[idx] = v;
}

// ---------------------------------------------------------------------------
extern "C" void kernel_launch(void* const* d_in, const int* in_sizes, int n_in,
                              void* d_out, int out_size)
{
    const float* x          = (const float*)d_in[0];
    const float* wavetables = (const float*)d_in[1];
    const float* tc_w1 = (const float*)d_in[2];  const float* tc_b1 = (const float*)d_in[3];
    const float* tc_w2 = (const float*)d_in[4];  const float* tc_b2 = (const float*)d_in[5];
    const float* tc_w3 = (const float*)d_in[6];  const float* tc_b3 = (const float*)d_in[7];
    const float* env_w1 = (const float*)d_in[8];  const float* env_b1 = (const float*)d_in[9];
    const float* env_w2 = (const float*)d_in[10]; const float* env_b2 = (const float*)d_in[11];
    const float* env_w3 = (const float*)d_in[12]; const float* env_b3 = (const float*)d_in[13];
    const float* fr_w1 = (const float*)d_in[14]; const float* fr_b1 = (const float*)d_in[15];
    const float* fr_w2 = (const float*)d_in[16]; const float* fr_b2 = (const float*)d_in[17];
    const float* fr_w3 = (const float*)d_in[18]; const float* fr_b3 = (const float*)d_in[19];

    float* out = (float*)d_out;
    float* out_sampled = out;                        // (8, 1, 32768)
    float* out_kernel  = out + BATCH * N_SAMPLES;    // (8, 32768, 512)

    head_kernel<<<3, 1024>>>(x,
        tc_w1, tc_b1, tc_w2, tc_b2, tc_w3, tc_b3,
        env_w1, env_b1, env_w2, env_b2, env_w3, env_b3,
        fr_w1, fr_b1, fr_w2, fr_b2, fr_w3, fr_b3);

    table_kernel<<<BATCH, 256>>>(wavetables);

    scan_kernel<<<BATCH, 1024>>>();

    sampled_kernel<<<(BATCH * N_SAMPLES * 32) / 256, 256>>>(out_sampled);

    const long long n_f4 = (long long)BATCH * N_SAMPLES * TABLE_SIZE / 4; // 33554432
    kern_writer<<<(unsigned)(n_f4 / 256), 256>>>(out_kernel);
}

// round 2
// speedup vs baseline: 1.9353x; 1.9353x over previous
#include <cuda_runtime.h>
#include <math.h>

#define MODEL_DIM 128
#define N_FRAMES 128
#define N_SAMPLES 32768
#define N_TABLES 16
#define TABLE_SIZE 512
#define BATCH 8
#define INV_STD 100.0f
#define GAUSS_SCALE 39.894228040143274f   // 1/(0.01*sqrt(2*pi))

// ------------------- scratch (static device globals; no runtime alloc) ---------
__device__ float g_env_frames[BATCH][N_FRAMES];   // (mlp out)^2
__device__ float g_freq_frames[BATCH][N_FRAMES];  // (mlp out)^2
__device__ float g_table[BATCH][TABLE_SIZE];      // normalized selected table
__device__ float g_values[BATCH];
__device__ int   g_idx[BATCH];
__device__ float g_phase[BATCH][N_SAMPLES];
__device__ float g_env[BATCH][N_SAMPLES];

// ---------------------------------------------------------------------------
// Head kernel: 3 blocks (tc / env / freq heads), 1024 threads each.
// ---------------------------------------------------------------------------
__global__ void head_kernel(const float* __restrict__ x,
                            const float* __restrict__ tc_w1, const float* __restrict__ tc_b1,
                            const float* __restrict__ tc_w2, const float* __restrict__ tc_b2,
                            const float* __restrict__ tc_w3, const float* __restrict__ tc_b3,
                            const float* __restrict__ env_w1, const float* __restrict__ env_b1,
                            const float* __restrict__ env_w2, const float* __restrict__ env_b2,
                            const float* __restrict__ env_w3, const float* __restrict__ env_b3,
                            const float* __restrict__ fr_w1, const float* __restrict__ fr_b1,
                            const float* __restrict__ fr_w2, const float* __restrict__ fr_b2,
                            const float* __restrict__ fr_w3, const float* __restrict__ fr_b3)
{
    const int head = blockIdx.x;
    const int tid = threadIdx.x;

    __shared__ float hs[BATCH * MODEL_DIM];
    __shared__ float h2[BATCH * MODEL_DIM];
    __shared__ float out_s[BATCH * 256];
    __shared__ float s_scores[BATCH * N_TABLES];

    const float *w1, *b1, *w2, *b2, *w3, *b3;
    int outdim;
    if (head == 0) { w1 = tc_w1;  b1 = tc_b1;  w2 = tc_w2;  b2 = tc_b2;  w3 = tc_w3;  b3 = tc_b3;  outdim = 256; }
    else if (head == 1) { w1 = env_w1; b1 = env_b1; w2 = env_w2; b2 = env_b2; w3 = env_w3; b3 = env_b3; outdim = 128; }
    else { w1 = fr_w1;  b1 = fr_b1;  w2 = fr_w2;  b2 = fr_b2;  w3 = fr_w3;  b3 = fr_b3;  outdim = 128; }

    hs[tid] = x[tid];
    __syncthreads();

    {
        int b = tid >> 7, o = tid & 127;
        float acc = b1[o];
        const float* hb = &hs[b * MODEL_DIM];
        #pragma unroll 8
        for (int i = 0; i < MODEL_DIM; i++)
            acc = fmaf(hb[i], w1[i * MODEL_DIM + o], acc);
        h2[tid] = (acc >= 0.0f) ? acc : 0.2f * acc;
    }
    __syncthreads();

    {
        int b = tid >> 7, o = tid & 127;
        float acc = b2[o];
        const float* hb = &h2[b * MODEL_DIM];
        #pragma unroll 8
        for (int i = 0; i < MODEL_DIM; i++)
            acc = fmaf(hb[i], w2[i * MODEL_DIM + o], acc);
        hs[tid] = (acc >= 0.0f) ? acc : 0.2f * acc;
    }
    __syncthreads();

    for (int oo = tid; oo < BATCH * outdim; oo += 1024) {
        int b = oo / outdim, o = oo - b * outdim;
        float acc = b3[o];
        const float* hb = &hs[b * MODEL_DIM];
        #pragma unroll 8
        for (int i = 0; i < MODEL_DIM; i++)
            acc = fmaf(hb[i], w3[i * outdim + o], acc);
        out_s[oo] = acc;
    }
    __syncthreads();

    if (head == 0) {
        if (tid < BATCH * N_TABLES) {
            int b = tid >> 4, n = tid & 15;
            float s = 0.0f;
            #pragma unroll
            for (int k = 0; k < 16; k++) s += out_s[b * 256 + n * 16 + k];
            s_scores[tid] = s * (1.0f / 16.0f);
        }
        __syncthreads();
        if (tid < BATCH) {
            float best = s_scores[tid * N_TABLES];
            int bi = 0;
            #pragma unroll
            for (int n = 1; n < N_TABLES; n++) {
                float v = s_scores[tid * N_TABLES + n];
                if (v > best) { best = v; bi = n; }
            }
            g_values[tid] = best;
            g_idx[tid] = bi;
        }
    } else if (head == 1) {
        float v = out_s[tid];
        ((float*)g_env_frames)[tid] = v * v;
    } else {
        float v = out_s[tid];
        ((float*)g_freq_frames)[tid] = v * v;
    }
}

// ---------------------------------------------------------------------------
// Normalize the selected wavetable per batch item: 8 blocks x 256 threads
// ---------------------------------------------------------------------------
__global__ void table_kernel(const float* __restrict__ wavetables)
{
    const int b = blockIdx.x;
    const int tid = threadIdx.x;
    const float* row = wavetables + g_idx[b] * TABLE_SIZE;

    __shared__ float sm[256];
    float m = fmaxf(row[tid], row[tid + 256]);
    sm[tid] = m;
    __syncthreads();
    for (int s = 128; s > 0; s >>= 1) {
        if (tid < s) sm[tid] = fmaxf(sm[tid], sm[tid + s]);
        __syncthreads();
    }
    float denom = sm[0] + 1e-8f;
    g_table[b][tid]       = row[tid] / denom;
    g_table[b][tid + 256] = row[tid + 256] / denom;
}

// ---------------------------------------------------------------------------
// Per-batch: interpolate env & freq to 32768 samples; block-scan cumsum of
// freq -> phase = cumsum % 1.  8 blocks x 1024 threads, 32 samples/thread.
// ---------------------------------------------------------------------------
__global__ void scan_kernel()
{
    const int b = blockIdx.x;
    const int tid = threadIdx.x;
    __shared__ float s_freq[N_FRAMES];
    __shared__ float s_env[N_FRAMES];
    __shared__ float s_w[32];

    if (tid < N_FRAMES) {
        s_freq[tid] = g_freq_frames[b][tid];
        s_env[tid]  = g_env_frames[b][tid];
    }
    __syncthreads();

    const int PER = 32;
    const int t0 = tid * PER;
    float vals[PER];
    float run = 0.0f;

    #pragma unroll
    for (int k = 0; k < PER; k++) {
        int t = t0 + k;
        float pos = ((float)t + 0.5f) * (1.0f / 256.0f) - 0.5f;
        pos = fminf(fmaxf(pos, 0.0f), 127.0f);
        int lo = (int)floorf(pos);
        int hi = min(lo + 1, 127);
        float w = pos - (float)lo;
        float f = s_freq[lo] * (1.0f - w) + s_freq[hi] * w;
        run += f;
        vals[k] = run;
        float e = s_env[lo] * (1.0f - w) + s_env[hi] * w;
        g_env[b][t] = e;
    }

    const int lane = tid & 31, wid = tid >> 5;
    float incl = run;
    #pragma unroll
    for (int off = 1; off < 32; off <<= 1) {
        float n = __shfl_up_sync(0xFFFFFFFFu, incl, off);
        if (lane >= off) incl += n;
    }
    if (lane == 31) s_w[wid] = incl;
    __syncthreads();
    if (wid == 0) {
        float v = s_w[lane];
        #pragma unroll
        for (int off = 1; off < 32; off <<= 1) {
            float n = __shfl_up_sync(0xFFFFFFFFu, v, off);
            if (lane >= off) v += n;
        }
        s_w[lane] = v;
    }
    __syncthreads();
    float excl = ((wid > 0) ? s_w[wid - 1] : 0.0f) + (incl - run);

    #pragma unroll
    for (int k = 0; k < PER; k++) {
        float c = excl + vals[k];
        g_phase[b][t0 + k] = fmodf(c, 1.0f);
    }
}

// ---------------------------------------------------------------------------
// Fused writer: warp per row (b,t). Writes the 512-col Gaussian row AND
// accumulates sampled[b][t] = (sum_j table[j]*K[j]) * env * values.
// Band test is warp-uniform -> out-of-band column blocks are pure zero STGs.
// ---------------------------------------------------------------------------
__global__ void fused_writer(float* __restrict__ out_kernel,
                             float* __restrict__ out_sampled)
{
    const int wg = (blockIdx.x * blockDim.x + threadIdx.x) >> 5;   // row id
    const int lane = threadIdx.x & 31;
    const int b = wg >> 15;
    const int t = wg & (N_SAMPLES - 1);

    const float phi  = g_phase[b][t];
    const float p100 = phi * INV_STD;
    const int   jc   = __float2int_rn(phi * 511.0f);
    const int   clo  = jc - 70;     // |z|<13.2 -> |c-jc| <= ~68; margin 70
    const int   chi  = jc + 70;

    float4* rowp = reinterpret_cast<float4*>(out_kernel) + ((long long)wg << 7);
    const float* tab = g_table[b];
    float acc = 0.0f;

    #pragma unroll
    for (int i = 0; i < 4; i++) {
        const int cblk = i * 128;                    // cols [cblk, cblk+127]
        if (chi < cblk || clo > cblk + 127) {
            // warp-uniform: whole 128-col block is zero
            float4 z4 = make_float4(0.0f, 0.0f, 0.0f, 0.0f);
            __stcs(&rowp[i * 32 + lane], z4);
        } else {
            const int col0 = (i * 32 + lane) * 4;
            float4 v;
            float* vp = &v.x;
            #pragma unroll
            for (int k = 0; k < 4; k++) {
                float z = fmaf((float)(col0 + k), INV_STD / 511.0f, -p100);
                float a = -0.5f * z * z;
                float e = (a > -87.0f) ? __expf(a) : 0.0f;
                vp[k] = GAUSS_SCALE * e;
                acc = fmaf(__ldg(&tab[col0 + k]), e, acc);
            }
            __stcs(&rowp[i * 32 + lane], v);
        }
    }

    #pragma unroll
    for (int off = 16; off > 0; off >>= 1)
        acc += __shfl_down_sync(0xFFFFFFFFu, acc, off);

    if (lane == 0)
        out_sampled[wg] = acc * GAUSS_SCALE * g_env[b][t] * g_values[b];
}

// ---------------------------------------------------------------------------
extern "C" void kernel_launch(void* const* d_in, const int* in_sizes, int n_in,
                              void* d_out, int out_size)
{
    const float* x          = (const float*)d_in[0];
    const float* wavetables = (const float*)d_in[1];
    const float* tc_w1 = (const float*)d_in[2];  const float* tc_b1 = (const float*)d_in[3];
    const float* tc_w2 = (const float*)d_in[4];  const float* tc_b2 = (const float*)d_in[5];
    const float* tc_w3 = (const float*)d_in[6];  const float* tc_b3 = (const float*)d_in[7];
    const float* env_w1 = (const float*)d_in[8];  const float* env_b1 = (const float*)d_in[9];
    const float* env_w2 = (const float*)d_in[10]; const float* env_b2 = (const float*)d_in[11];
    const float* env_w3 = (const float*)d_in[12]; const float* env_b3 = (const float*)d_in[13];
    const float* fr_w1 = (const float*)d_in[14]; const float* fr_b1 = (const float*)d_in[15];
    const float* fr_w2 = (const float*)d_in[16]; const float* fr_b2 = (const float*)d_in[17];
    const float* fr_w3 = (const float*)d_in[18]; const float* fr_b3 = (const float*)d_in[19];

    float* out = (float*)d_out;
    float* out_sampled = out;                        // (8, 1, 32768)
    float* out_kernel  = out + BATCH * N_SAMPLES;    // (8, 32768, 512)

    head_kernel<<<3, 1024>>>(x,
        tc_w1, tc_b1, tc_w2, tc_b2, tc_w3, tc_b3,
        env_w1, env_b1, env_w2, env_b2, env_w3, env_b3,
        fr_w1, fr_b1, fr_w2, fr_b2, fr_w3, fr_b3);

    table_kernel<<<BATCH, 256>>>(wavetables);

    scan_kernel<<<BATCH, 1024>>>();

    // one warp per (b, t) row: 262144 warps, 8 warps/block -> 32768 blocks
    fused_writer<<<(BATCH * N_SAMPLES) / 8, 256>>>(out_kernel, out_sampled);
}

// round 3
// speedup vs baseline: 2.2201x; 1.1472x over previous
#include <cuda_runtime.h>
#include <math.h>

#define MODEL_DIM 128
#define N_FRAMES 128
#define N_SAMPLES 32768
#define N_TABLES 16
#define TABLE_SIZE 512
#define BATCH 8
#define INV_STD 100.0f
#define GAUSS_SCALE 39.894228040143274f   // 1/(0.01*sqrt(2*pi))

// ------------------- scratch (static device globals; no runtime alloc) ---------
__device__ float g_table[BATCH][TABLE_SIZE];      // normalized selected table
__device__ float g_values[BATCH];
__device__ float g_phase[BATCH][N_SAMPLES];
__device__ float g_env[BATCH][N_SAMPLES];

// ---------------------------------------------------------------------------
// prep_kernel: 9 blocks x 1024 threads, NO cross-block dependencies.
//   block 0   : tc head for all 8 rows -> argmax/max -> normalize selected tables
//   block 1+b : env & freq MLPs for batch row b only, then interp + scan -> phase/env
// ---------------------------------------------------------------------------
__global__ void prep_kernel(const float* __restrict__ x,
                            const float* __restrict__ wavetables,
                            const float* __restrict__ tc_w1, const float* __restrict__ tc_b1,
                            const float* __restrict__ tc_w2, const float* __restrict__ tc_b2,
                            const float* __restrict__ tc_w3, const float* __restrict__ tc_b3,
                            const float* __restrict__ env_w1, const float* __restrict__ env_b1,
                            const float* __restrict__ env_w2, const float* __restrict__ env_b2,
                            const float* __restrict__ env_w3, const float* __restrict__ env_b3,
                            const float* __restrict__ fr_w1, const float* __restrict__ fr_b1,
                            const float* __restrict__ fr_w2, const float* __restrict__ fr_b2,
                            const float* __restrict__ fr_w3, const float* __restrict__ fr_b3)
{
    const int tid = threadIdx.x;

    if (blockIdx.x == 0) {
        // ---------------- tc head, all 8 batch rows ----------------
        __shared__ float hs[BATCH * MODEL_DIM];
        __shared__ float h2[BATCH * MODEL_DIM];
        __shared__ float out_s[BATCH * 256];
        __shared__ float s_scores[BATCH * N_TABLES];
        __shared__ int   s_idx[BATCH];
        __shared__ float s_den[BATCH];

        hs[tid] = x[tid];
        __syncthreads();

        {   // layer1
            int b = tid >> 7, o = tid & 127;
            float acc = tc_b1[o];
            const float* hb = &hs[b * MODEL_DIM];
            #pragma unroll 8
            for (int i = 0; i < MODEL_DIM; i++)
                acc = fmaf(hb[i], tc_w1[i * MODEL_DIM + o], acc);
            h2[tid] = (acc >= 0.0f) ? acc : 0.2f * acc;
        }
        __syncthreads();
        {   // layer2
            int b = tid >> 7, o = tid & 127;
            float acc = tc_b2[o];
            const float* hb = &h2[b * MODEL_DIM];
            #pragma unroll 8
            for (int i = 0; i < MODEL_DIM; i++)
                acc = fmaf(hb[i], tc_w2[i * MODEL_DIM + o], acc);
            hs[tid] = (acc >= 0.0f) ? acc : 0.2f * acc;
        }
        __syncthreads();
        // layer3: outdim 256 -> 2048 outputs, 2 per thread
        #pragma unroll
        for (int r = 0; r < 2; r++) {
            int oo = tid + r * 1024;
            int b = oo >> 8, o = oo & 255;
            float acc = tc_b3[o];
            const float* hb = &hs[b * MODEL_DIM];
            #pragma unroll 8
            for (int i = 0; i < MODEL_DIM; i++)
                acc = fmaf(hb[i], tc_w3[i * 256 + o], acc);
            out_s[oo] = acc;
        }
        __syncthreads();

        if (tid < BATCH * N_TABLES) {
            int b = tid >> 4, n = tid & 15;
            float s = 0.0f;
            #pragma unroll
            for (int k = 0; k < 16; k++) s += out_s[b * 256 + n * 16 + k];
            s_scores[tid] = s * (1.0f / 16.0f);
        }
        __syncthreads();
        if (tid < BATCH) {
            float best = s_scores[tid * N_TABLES];
            int bi = 0;
            #pragma unroll
            for (int n = 1; n < N_TABLES; n++) {
                float v = s_scores[tid * N_TABLES + n];
                if (v > best) { best = v; bi = n; }   // first-max ties == argmax
            }
            g_values[tid] = best;
            s_idx[tid] = bi;
        }
        __syncthreads();

        // ------------- normalize selected tables: warp w handles batch w -------------
        const int wid = tid >> 5, lane = tid & 31;
        if (wid < BATCH) {
            const float* row = wavetables + s_idx[wid] * TABLE_SIZE;
            float m = -3.4e38f;
            #pragma unroll
            for (int i = 0; i < 16; i++)
                m = fmaxf(m, __ldg(&row[lane + i * 32]));
            #pragma unroll
            for (int off = 16; off > 0; off >>= 1)
                m = fmaxf(m, __shfl_xor_sync(0xFFFFFFFFu, m, off));
            float denom = m + 1e-8f;
            if (lane == 0) s_den[wid] = denom;   // (unused elsewhere; keeps pattern clear)
            #pragma unroll
            for (int i = 0; i < 16; i++) {
                int j = lane + i * 32;
                g_table[wid][j] = __ldg(&row[j]) / denom;
            }
        }
        return;
    }

    // ---------------- blocks 1..8: per-batch env/freq MLP + interp + scan ----------
    const int b = blockIdx.x - 1;

    __shared__ float s_x[MODEL_DIM];
    __shared__ float s_part[8 * MODEL_DIM];
    __shared__ float s_h[MODEL_DIM];
    __shared__ float s_env[N_FRAMES];
    __shared__ float s_freq[N_FRAMES];
    __shared__ float s_w[32];

    if (tid < MODEL_DIM) s_x[tid] = x[b * MODEL_DIM + tid];
    __syncthreads();

    const int r = tid >> 7;        // 0..7 : k-slice
    const int o = tid & 127;       // output index

    // helper macro-ish: run one 3-layer MLP writing squared output to dst[]
    // layer: partials over k in [16r,16r+16), reduce 8, bias+act
    #define MLP3(W1, B1, W2, B2, W3, B3, DST)                                   \
    {                                                                            \
        float p = 0.0f;                                                          \
        {                                                                        \
            const int k0 = r * 16;                                               \
            _Pragma("unroll")                                                    \
            for (int k = 0; k < 16; k++)                                         \
                p = fmaf(s_x[k0 + k], W1[(k0 + k) * MODEL_DIM + o], p);          \
            s_part[r * MODEL_DIM + o] = p;                                       \
        }                                                                        \
        __syncthreads();                                                         \
        if (tid < MODEL_DIM) {                                                   \
            float acc = B1[tid];                                                 \
            _Pragma("unroll")                                                    \
            for (int rr = 0; rr < 8; rr++) acc += s_part[rr * MODEL_DIM + tid];  \
            s_h[tid] = (acc >= 0.0f) ? acc : 0.2f * acc;                         \
        }                                                                        \
        __syncthreads();                                                         \
        p = 0.0f;                                                                \
        {                                                                        \
            const int k0 = r * 16;                                               \
            _Pragma("unroll")                                                    \
            for (int k = 0; k < 16; k++)                                         \
                p = fmaf(s_h[k0 + k], W2[(k0 + k) * MODEL_DIM + o], p);          \
            s_part[r * MODEL_DIM + o] = p;                                       \
        }                                                                        \
        __syncthreads();                                                         \
        if (tid < MODEL_DIM) {                                                   \
            float acc = B2[tid];                                                 \
            _Pragma("unroll")                                                    \
            for (int rr = 0; rr < 8; rr++) acc += s_part[rr * MODEL_DIM + tid];  \
            s_part[tid] = (acc >= 0.0f) ? acc : 0.2f * acc;  /* reuse row 0 */   \
        }                                                                        \
        __syncthreads();                                                         \
        if (tid < MODEL_DIM) s_h[tid] = s_part[tid];                             \
        __syncthreads();                                                         \
        p = 0.0f;                                                                \
        {                                                                        \
            const int k0 = r * 16;                                               \
            _Pragma("unroll")                                                    \
            for (int k = 0; k < 16; k++)                                         \
                p = fmaf(s_h[k0 + k], W3[(k0 + k) * N_FRAMES + o], p);           \
            s_part[r * MODEL_DIM + o] = p;                                       \
        }                                                                        \
        __syncthreads();                                                         \
        if (tid < N_FRAMES) {                                                    \
            float acc = B3[tid];                                                 \
            _Pragma("unroll")                                                    \
            for (int rr = 0; rr < 8; rr++) acc += s_part[rr * MODEL_DIM + tid];  \
            DST[tid] = acc * acc;  /* squared */                                 \
        }                                                                        \
        __syncthreads();                                                         \
    }

    MLP3(env_w1, env_b1, env_w2, env_b2, env_w3, env_b3, s_env)
    MLP3(fr_w1,  fr_b1,  fr_w2,  fr_b2,  fr_w3,  fr_b3,  s_freq)

    // --------------- interpolate to 32768 + cumsum scan -> phase ---------------
    const int PER = 32;
    const int t0 = tid * PER;
    float vals[PER];
    float run = 0.0f;

    #pragma unroll
    for (int k = 0; k < PER; k++) {
        int t = t0 + k;
        float pos = ((float)t + 0.5f) * (1.0f / 256.0f) - 0.5f;
        pos = fminf(fmaxf(pos, 0.0f), 127.0f);
        int lo = (int)floorf(pos);
        int hi = min(lo + 1, 127);
        float w = pos - (float)lo;
        float f = s_freq[lo] * (1.0f - w) + s_freq[hi] * w;
        run += f;
        vals[k] = run;
        float e = s_env[lo] * (1.0f - w) + s_env[hi] * w;
        g_env[b][t] = e;
    }

    const int lane = tid & 31, wid = tid >> 5;
    float incl = run;
    #pragma unroll
    for (int off = 1; off < 32; off <<= 1) {
        float n = __shfl_up_sync(0xFFFFFFFFu, incl, off);
        if (lane >= off) incl += n;
    }
    if (lane == 31) s_w[wid] = incl;
    __syncthreads();
    if (wid == 0) {
        float v = s_w[lane];
        #pragma unroll
        for (int off = 1; off < 32; off <<= 1) {
            float n = __shfl_up_sync(0xFFFFFFFFu, v, off);
            if (lane >= off) v += n;
        }
        s_w[lane] = v;
    }
    __syncthreads();
    float excl = ((wid > 0) ? s_w[wid - 1] : 0.0f) + (incl - run);

    #pragma unroll
    for (int k = 0; k < PER; k++) {
        float c = excl + vals[k];
        g_phase[b][t0 + k] = fmodf(c, 1.0f);
    }
}

// ---------------------------------------------------------------------------
// Fused writer: warp per row (b,t). Writes the 512-col Gaussian row AND
// accumulates sampled[b][t] = (sum_j table[j]*K[j]) * env * values.
// Band test is warp-uniform -> out-of-band column blocks are pure zero STGs.
// ---------------------------------------------------------------------------
__global__ void fused_writer(float* __restrict__ out_kernel,
                             float* __restrict__ out_sampled)
{
    const int wg = (blockIdx.x * blockDim.x + threadIdx.x) >> 5;   // row id
    const int lane = threadIdx.x & 31;
    const int b = wg >> 15;
    const int t = wg & (N_SAMPLES - 1);

    const float phi  = g_phase[b][t];
    const float p100 = phi * INV_STD;
    const int   jc   = __float2int_rn(phi * 511.0f);
    const int   clo  = jc - 70;     // |z|<13.2 -> |c-jc| <= ~68; margin 70
    const int   chi  = jc + 70;

    float4* rowp = reinterpret_cast<float4*>(out_kernel) + ((long long)wg << 7);
    const float* tab = g_table[b];
    float acc = 0.0f;

    #pragma unroll
    for (int i = 0; i < 4; i++) {
        const int cblk = i * 128;                    // cols [cblk, cblk+127]
        if (chi < cblk || clo > cblk + 127) {
            float4 z4 = make_float4(0.0f, 0.0f, 0.0f, 0.0f);
            __stcs(&rowp[i * 32 + lane], z4);
        } else {
            const int col0 = (i * 32 + lane) * 4;
            float4 v;
            float* vp = &v.x;
            #pragma unroll
            for (int k = 0; k < 4; k++) {
                float z = fmaf((float)(col0 + k), INV_STD / 511.0f, -p100);
                float a = -0.5f * z * z;
                float e = (a > -87.0f) ? __expf(a) : 0.0f;
                vp[k] = GAUSS_SCALE * e;
                acc = fmaf(__ldg(&tab[col0 + k]), e, acc);
            }
            __stcs(&rowp[i * 32 + lane], v);
        }
    }

    #pragma unroll
    for (int off = 16; off > 0; off >>= 1)
        acc += __shfl_down_sync(0xFFFFFFFFu, acc, off);

    if (lane == 0)
        out_sampled[wg] = acc * GAUSS_SCALE * g_env[b][t] * g_values[b];
}

// ---------------------------------------------------------------------------
extern "C" void kernel_launch(void* const* d_in, const int* in_sizes, int n_in,
                              void* d_out, int out_size)
{
    const float* x          = (const float*)d_in[0];
    const float* wavetables = (const float*)d_in[1];
    const float* tc_w1 = (const float*)d_in[2];  const float* tc_b1 = (const float*)d_in[3];
    const float* tc_w2 = (const float*)d_in[4];  const float* tc_b2 = (const float*)d_in[5];
    const float* tc_w3 = (const float*)d_in[6];  const float* tc_b3 = (const float*)d_in[7];
    const float* env_w1 = (const float*)d_in[8];  const float* env_b1 = (const float*)d_in[9];
    const float* env_w2 = (const float*)d_in[10]; const float* env_b2 = (const float*)d_in[11];
    const float* env_w3 = (const float*)d_in[12]; const float* env_b3 = (const float*)d_in[13];
    const float* fr_w1 = (const float*)d_in[14]; const float* fr_b1 = (const float*)d_in[15];
    const float* fr_w2 = (const float*)d_in[16]; const float* fr_b2 = (const float*)d_in[17];
    const float* fr_w3 = (const float*)d_in[18]; const float* fr_b3 = (const float*)d_in[19];

    float* out = (float*)d_out;
    float* out_sampled = out;                        // (8, 1, 32768)
    float* out_kernel  = out + BATCH * N_SAMPLES;    // (8, 32768, 512)

    prep_kernel<<<9, 1024>>>(x, wavetables,
        tc_w1, tc_b1, tc_w2, tc_b2, tc_w3, tc_b3,
        env_w1, env_b1, env_w2, env_b2, env_w3, env_b3,
        fr_w1, fr_b1, fr_w2, fr_b2, fr_w3, fr_b3);

    // one warp per (b, t) row: 262144 warps, 8 warps/block -> 32768 blocks
    fused_writer<<<(BATCH * N_SAMPLES) / 8, 256>>>(out_kernel, out_sampled);
}